// round 3
// baseline (speedup 1.0000x reference)
#include <cuda_runtime.h>
#include <cuda_bf16.h>
#include <math_constants.h>
#include <math.h>

#define NTOT  8192
#define BHALF 4096
#define DDIM  128
#define KDIM  8192

// ---------------- device scratch (static, no allocations) ----------------
__device__ __nv_bfloat16 g_h[NTOT * DDIM];      // concat(h_i,h_j) in bf16
__device__ __nv_bfloat16 g_axT[DDIM * KDIM];    // all_x transposed [d][k], bf16
__device__ float g_xs2[BHALF];                  // ||sub_x_i||^2
__device__ float g_ax2[KDIM];                   // ||all_x_k||^2
__device__ float g_c[KDIM];                     // column sums of sub_graph
__device__ float g_acc[4];                      // 0: contrastive sum, 1: t1, 2: t3

// ---------------- helpers ----------------
__device__ __forceinline__ void mma_bf16(float* c, const unsigned* a, unsigned b0, unsigned b1) {
    asm volatile(
        "mma.sync.aligned.m16n8k16.row.col.f32.bf16.bf16.f32 "
        "{%0,%1,%2,%3}, {%4,%5,%6,%7}, {%8,%9}, {%0,%1,%2,%3};\n"
        : "+f"(c[0]), "+f"(c[1]), "+f"(c[2]), "+f"(c[3])
        : "r"(a[0]), "r"(a[1]), "r"(a[2]), "r"(a[3]), "r"(b0), "r"(b1));
}

__device__ __forceinline__ unsigned pack_bf2(float x, float y) {
    __nv_bfloat162 b = __floats2bfloat162_rn(x, y);
    return *reinterpret_cast<unsigned*>(&b);
}

// ---------------- prep: h concat->bf16, norms, zero accumulators ----------------
__global__ void __launch_bounds__(256) prep_kernel(const float* __restrict__ h_i,
                                                   const float* __restrict__ h_j,
                                                   const float* __restrict__ sub_x,
                                                   const float* __restrict__ all_x) {
    int tid = blockIdx.x * blockDim.x + threadIdx.x;
    int nth = gridDim.x * blockDim.x;

    int nh2 = NTOT * DDIM / 2;
    for (int idx = tid; idx < nh2; idx += nth) {
        int el  = idx << 1;
        int row = el >> 7;
        int col = el & 127;
        const float* src = (row < BHALF) ? (h_i + row * DDIM + col)
                                         : (h_j + (row - BHALF) * DDIM + col);
        float2 v = *reinterpret_cast<const float2*>(src);
        reinterpret_cast<__nv_bfloat162*>(g_h)[idx] = __floats2bfloat162_rn(v.x, v.y);
    }

    int wid = tid >> 5, lane = tid & 31, nw = nth >> 5;
    for (int r = wid; r < BHALF; r += nw) {
        float4 a = reinterpret_cast<const float4*>(sub_x + r * DDIM)[lane];
        float s = a.x*a.x + a.y*a.y + a.z*a.z + a.w*a.w;
        #pragma unroll
        for (int o = 16; o; o >>= 1) s += __shfl_xor_sync(0xffffffffu, s, o);
        if (lane == 0) g_xs2[r] = s;
    }
    for (int r = wid; r < KDIM; r += nw) {
        float4 a = reinterpret_cast<const float4*>(all_x + r * DDIM)[lane];
        float s = a.x*a.x + a.y*a.y + a.z*a.z + a.w*a.w;
        #pragma unroll
        for (int o = 16; o; o >>= 1) s += __shfl_xor_sync(0xffffffffu, s, o);
        if (lane == 0) g_ax2[r] = s;
    }

    for (int i = tid; i < KDIM; i += nth) g_c[i] = 0.f;
    if (blockIdx.x == 0 && tid < 4) g_acc[tid] = 0.f;
}

// ---------------- transpose all_x -> g_axT[d][k] (bf16), smem-tiled ----------------
__global__ void __launch_bounds__(256) transpose_ax(const float* __restrict__ all_x) {
    __shared__ float t[32][33];
    int k0 = blockIdx.x * 32;  // 256 blocks
    int d0 = blockIdx.y * 32;  // 4 blocks
    int tx = threadIdx.x & 31, ty = threadIdx.x >> 5;  // ty 0..7
    #pragma unroll
    for (int j = 0; j < 4; j++) {
        int k = k0 + ty + j * 8;
        t[ty + j * 8][tx] = all_x[k * DDIM + d0 + tx];
    }
    __syncthreads();
    #pragma unroll
    for (int j = 0; j < 4; j++) {
        int d = d0 + ty + j * 8;
        g_axT[d * KDIM + k0 + tx] = __float2bfloat16(t[tx][ty + j * 8]);
    }
}

// ---------------- fused contrastive: sim tiles + online logsumexp ----------------
#define CPAD 136  // 128 + 8 bf16 pitch, 272B (17*16) -> uint4-aligned rows

__global__ void __launch_bounds__(256) contrastive_kernel() {
    __shared__ __nv_bfloat16 As[64 * CPAD];
    __shared__ __nv_bfloat16 Bs[64 * CPAD];
    __shared__ float m_run[64], s_run[64], pos_s[64];
    __shared__ float stage_m[64][2], stage_s[64][2];

    int tid = threadIdx.x;
    int warp = tid >> 5, lane = tid & 31;
    int wm = warp >> 1, wn = warp & 1;           // 4 row-warps x 2 col-warps
    int g = lane >> 2, tig = lane & 3;
    int rowBlock = blockIdx.x * 64;

    for (int i = tid; i < 1024; i += 256) {      // 64 rows x 16 uint4
        int r = i >> 4, c8 = i & 15;
        *reinterpret_cast<uint4*>(As + r * CPAD + c8 * 8) =
            reinterpret_cast<const uint4*>(g_h + (rowBlock + r) * DDIM)[c8];
    }
    if (tid < 64) { m_run[tid] = -CUDART_INF_F; s_run[tid] = 0.f; pos_s[tid] = 0.f; }
    __syncthreads();

    // Preload A fragments (reused across all 128 column tiles)
    unsigned a_frag[8][4];
    int r0 = wm * 16;
    #pragma unroll
    for (int ks = 0; ks < 8; ks++) {
        int kc = ks * 16 + tig * 2;
        a_frag[ks][0] = *reinterpret_cast<const unsigned*>(As + (r0 + g)     * CPAD + kc);
        a_frag[ks][1] = *reinterpret_cast<const unsigned*>(As + (r0 + g + 8) * CPAD + kc);
        a_frag[ks][2] = *reinterpret_cast<const unsigned*>(As + (r0 + g)     * CPAD + kc + 8);
        a_frag[ks][3] = *reinterpret_cast<const unsigned*>(As + (r0 + g + 8) * CPAD + kc + 8);
    }

    int rowG0 = rowBlock + r0 + g;               // this thread's rows: rowG0, rowG0+8
    int lr0 = r0 + g, lr1 = r0 + g + 8;
    int p0 = (rowG0 + BHALF) & (NTOT - 1);
    int p1 = (rowG0 + 8 + BHALF) & (NTOT - 1);

    for (int ct = 0; ct < NTOT / 64; ct++) {
        __syncthreads();
        for (int i = tid; i < 1024; i += 256) {
            int r = i >> 4, c8 = i & 15;
            *reinterpret_cast<uint4*>(Bs + r * CPAD + c8 * 8) =
                reinterpret_cast<const uint4*>(g_h + (ct * 64 + r) * DDIM)[c8];
        }
        __syncthreads();

        float acc[4][4];
        #pragma unroll
        for (int nt = 0; nt < 4; nt++)
            acc[nt][0] = acc[nt][1] = acc[nt][2] = acc[nt][3] = 0.f;

        #pragma unroll
        for (int ks = 0; ks < 8; ks++) {
            #pragma unroll
            for (int nt = 0; nt < 4; nt++) {
                const __nv_bfloat16* bp = Bs + (wn * 32 + nt * 8 + g) * CPAD + ks * 16 + tig * 2;
                unsigned b0 = *reinterpret_cast<const unsigned*>(bp);
                unsigned b1 = *reinterpret_cast<const unsigned*>(bp + 8);
                mma_bf16(acc[nt], a_frag[ks], b0, b1);
            }
        }

        // epilogue: scale by 1/T=2, capture positives, mask diagonal, tile (max,sumexp)
        float vv[2][8];
        #pragma unroll
        for (int nt = 0; nt < 4; nt++) {
            int jcol = ct * 64 + wn * 32 + nt * 8 + tig * 2;
            #pragma unroll
            for (int q = 0; q < 2; q++) {
                int jc = jcol + q;
                float x0 = acc[nt][q]     * 2.0f;   // row rowG0
                float x1 = acc[nt][2 + q] * 2.0f;   // row rowG0+8
                if (jc == p0) pos_s[lr0] = x0;
                if (jc == p1) pos_s[lr1] = x1;
                if (jc == rowG0)     x0 = -CUDART_INF_F;
                if (jc == rowG0 + 8) x1 = -CUDART_INF_F;
                vv[0][nt * 2 + q] = x0;
                vv[1][nt * 2 + q] = x1;
            }
        }
        #pragma unroll
        for (int rr = 0; rr < 2; rr++) {
            float tm = vv[rr][0];
            #pragma unroll
            for (int q = 1; q < 8; q++) tm = fmaxf(tm, vv[rr][q]);
            tm = fmaxf(tm, __shfl_xor_sync(0xffffffffu, tm, 1));
            tm = fmaxf(tm, __shfl_xor_sync(0xffffffffu, tm, 2));
            float ts = 0.f;
            #pragma unroll
            for (int q = 0; q < 8; q++) ts += __expf(vv[rr][q] - tm);
            ts += __shfl_xor_sync(0xffffffffu, ts, 1);
            ts += __shfl_xor_sync(0xffffffffu, ts, 2);
            if (tig == 0) {
                int lr = rr ? lr1 : lr0;
                stage_m[lr][wn] = tm;
                stage_s[lr][wn] = ts;
            }
        }
        __syncthreads();
        if (tid < 64) {
            float m0 = m_run[tid], s0 = s_run[tid];
            float m1 = stage_m[tid][0], s1 = stage_s[tid][0];
            float m2 = stage_m[tid][1], s2 = stage_s[tid][1];
            float nm = fmaxf(m0, fmaxf(m1, m2));
            s_run[tid] = s0 * __expf(m0 - nm) + s1 * __expf(m1 - nm) + s2 * __expf(m2 - nm);
            m_run[tid] = nm;
        }
    }
    __syncthreads();

    float v = 0.f;
    if (tid < 64) v = m_run[tid] + logf(s_run[tid]) - pos_s[tid];
    #pragma unroll
    for (int o = 16; o; o >>= 1) v += __shfl_xor_sync(0xffffffffu, v, o);
    if (tid < 64 && lane == 0) atomicAdd(&g_acc[0], v);
}

// ---------------- fused graph pass over sub_graph ----------------
#define GP  36   // fp32 G tile pitch (144B = 9*16, float4-aligned)
#define KPX 40   // bf16 axT tile pitch (80B = 5*16, uint4-aligned)

__global__ void __launch_bounds__(256) graph_kernel(const float* __restrict__ G,
                                                    const float* __restrict__ sub_x) {
    __shared__ float Gs[128 * GP];             // fp32 tile (exact row/col sums)
    __shared__ __nv_bfloat16 Xs[128 * KPX];    // axT tile [d][k]
    __shared__ float c_loc[2048];

    int tid = threadIdx.x;
    int warp = tid >> 5, lane = tid & 31;
    int g = lane >> 2, tig = lane & 3;
    int rb  = blockIdx.x & 31;    // row tile 0..31
    int ksp = blockIdx.x >> 5;    // K split 0..3
    int rowBase = rb * 128;
    int kBase   = ksp * 2048;

    for (int i = tid; i < 2048; i += 256) c_loc[i] = 0.f;

    float acc[16][4];
    #pragma unroll
    for (int nt = 0; nt < 16; nt++)
        acc[nt][0] = acc[nt][1] = acc[nt][2] = acc[nt][3] = 0.f;
    float rsum[4] = {0.f, 0.f, 0.f, 0.f};

    const int r0 = warp * 16;

    for (int kt = 0; kt < 64; kt++) {
        int k0 = kBase + kt * 32;
        __syncthreads();
        // load G tile fp32 [128][32] + row-sum partials
        #pragma unroll
        for (int rd = 0; rd < 4; rd++) {
            int idx = tid + rd * 256;
            int r = idx >> 3, c4 = idx & 7;
            float4 v = reinterpret_cast<const float4*>(G + (rowBase + r) * KDIM + k0)[c4];
            *reinterpret_cast<float4*>(Gs + r * GP + c4 * 4) = v;
            rsum[rd] += v.x + v.y + v.z + v.w;
        }
        // load axT tile [128 d][32 k]
        for (int i = tid; i < 512; i += 256) {
            int d = i >> 2, q = i & 3;
            *reinterpret_cast<uint4*>(Xs + d * KPX + q * 8) =
                *reinterpret_cast<const uint4*>(g_axT + d * KDIM + k0 + q * 8);
        }
        __syncthreads();

        // column sums (fp32 from Gs)
        {
            int col = tid & 31, grp = tid >> 5;
            float cs = 0.f;
            #pragma unroll
            for (int rr = 0; rr < 16; rr++) cs += Gs[(grp * 16 + rr) * GP + col];
            atomicAdd(&c_loc[kt * 32 + col], cs);
        }

        // mma: A = G (fp32->bf16 on the fly), B = axT
        #pragma unroll
        for (int ks = 0; ks < 2; ks++) {
            unsigned af[4];
            int kc = ks * 16 + tig * 2;
            float2 v0 = *reinterpret_cast<const float2*>(Gs + (r0 + g)     * GP + kc);
            float2 v1 = *reinterpret_cast<const float2*>(Gs + (r0 + g + 8) * GP + kc);
            float2 v2 = *reinterpret_cast<const float2*>(Gs + (r0 + g)     * GP + kc + 8);
            float2 v3 = *reinterpret_cast<const float2*>(Gs + (r0 + g + 8) * GP + kc + 8);
            af[0] = pack_bf2(v0.x, v0.y);
            af[1] = pack_bf2(v1.x, v1.y);
            af[2] = pack_bf2(v2.x, v2.y);
            af[3] = pack_bf2(v3.x, v3.y);
            #pragma unroll
            for (int nt = 0; nt < 16; nt++) {
                const __nv_bfloat16* bp = Xs + (nt * 8 + g) * KPX + ks * 16 + tig * 2;
                unsigned b0 = *reinterpret_cast<const unsigned*>(bp);
                unsigned b1 = *reinterpret_cast<const unsigned*>(bp + 8);
                mma_bf16(acc[nt], af, b0, b1);
            }
        }
    }
    __syncthreads();

    // flush column-sum partials
    for (int i = tid; i < 2048; i += 256) atomicAdd(&g_c[kBase + i], c_loc[i]);

    // t3 partial: acc . sub_x
    float t3p = 0.f;
    int rg0 = rowBase + r0 + g;
    #pragma unroll
    for (int nt = 0; nt < 16; nt++) {
        int d = nt * 8 + tig * 2;
        float2 s0 = *reinterpret_cast<const float2*>(sub_x + rg0 * DDIM + d);
        float2 s1 = *reinterpret_cast<const float2*>(sub_x + (rg0 + 8) * DDIM + d);
        t3p += acc[nt][0] * s0.x + acc[nt][1] * s0.y + acc[nt][2] * s1.x + acc[nt][3] * s1.y;
    }
    #pragma unroll
    for (int o = 16; o; o >>= 1) t3p += __shfl_xor_sync(0xffffffffu, t3p, o);
    if (lane == 0) atomicAdd(&g_acc[2], t3p);

    // t1 partial: row-sum * ||sub_x||^2
    float t1p = 0.f;
    #pragma unroll
    for (int rd = 0; rd < 4; rd++) {
        float rs = rsum[rd];
        #pragma unroll
        for (int o = 1; o < 8; o <<= 1) rs += __shfl_xor_sync(0xffffffffu, rs, o);
        if ((lane & 7) == 0)
            t1p += rs * g_xs2[rowBase + (tid >> 3) + rd * 32];
    }
    t1p += __shfl_xor_sync(0xffffffffu, t1p, 8);
    t1p += __shfl_xor_sync(0xffffffffu, t1p, 16);
    if (lane == 0) atomicAdd(&g_acc[1], t1p);
}

// ---------------- finalize: t2 + combine ----------------
__global__ void __launch_bounds__(256) finalize_kernel(float* __restrict__ out) {
    __shared__ float red[8];
    int tid = threadIdx.x;
    float t2 = 0.f;
    for (int k = tid; k < KDIM; k += 256) t2 += g_c[k] * g_ax2[k];
    #pragma unroll
    for (int o = 16; o; o >>= 1) t2 += __shfl_xor_sync(0xffffffffu, t2, o);
    if ((tid & 31) == 0) red[tid >> 5] = t2;
    __syncthreads();
    if (tid == 0) {
        float t2s = 0.f;
        #pragma unroll
        for (int i = 0; i < 8; i++) t2s += red[i];
        float contr = g_acc[0] / (float)NTOT;
        float graph = (g_acc[1] + t2s - 2.0f * g_acc[2]) / ((float)BHALF * (float)KDIM);
        out[0] = contr + graph;
    }
}

// ---------------- launch ----------------
extern "C" void kernel_launch(void* const* d_in, const int* in_sizes, int n_in,
                              void* d_out, int out_size) {
    (void)in_sizes; (void)n_in; (void)out_size;
    const float* h_i   = (const float*)d_in[0];
    const float* h_j   = (const float*)d_in[1];
    const float* G     = (const float*)d_in[2];
    const float* sub_x = (const float*)d_in[3];
    const float* all_x = (const float*)d_in[4];
    float* out = (float*)d_out;

    prep_kernel<<<512, 256>>>(h_i, h_j, sub_x, all_x);
    transpose_ax<<<dim3(256, 4), 256>>>(all_x);
    contrastive_kernel<<<128, 256>>>();
    graph_kernel<<<128, 256>>>(G, sub_x);
    finalize_kernel<<<1, 256>>>(out);
}

// round 5
// speedup vs baseline: 1.9887x; 1.9887x over previous
#include <cuda_runtime.h>
#include <cuda_bf16.h>
#include <math_constants.h>
#include <math.h>

#define NTOT  8192
#define BHALF 4096
#define DDIM  128
#define KDIM  8192

// ---------------- device scratch ----------------
__device__ __nv_bfloat16 g_h[NTOT * DDIM];
__device__ __nv_bfloat16 g_axT[DDIM * KDIM];
__device__ float g_xs2[BHALF];
__device__ float g_ax2[KDIM];
__device__ float g_c[KDIM];
__device__ float g_acc[4];   // 0: contrastive, 1: t1, 2: t3

// ---------------- helpers ----------------
__device__ __forceinline__ void mma_bf16(float* c, const unsigned* a, unsigned b0, unsigned b1) {
    asm volatile(
        "mma.sync.aligned.m16n8k16.row.col.f32.bf16.bf16.f32 "
        "{%0,%1,%2,%3}, {%4,%5,%6,%7}, {%8,%9}, {%0,%1,%2,%3};\n"
        : "+f"(c[0]), "+f"(c[1]), "+f"(c[2]), "+f"(c[3])
        : "r"(a[0]), "r"(a[1]), "r"(a[2]), "r"(a[3]), "r"(b0), "r"(b1));
}
__device__ __forceinline__ unsigned pack_bf2(float x, float y) {
    __nv_bfloat162 b = __floats2bfloat162_rn(x, y);
    return *reinterpret_cast<unsigned*>(&b);
}
__device__ __forceinline__ void cp16(unsigned dst, const void* src) {
    asm volatile("cp.async.cg.shared.global [%0], [%1], 16;\n" :: "r"(dst), "l"(src));
}
__device__ __forceinline__ void cp_commit() { asm volatile("cp.async.commit_group;\n"); }
template<int N> __device__ __forceinline__ void cp_wait() {
    asm volatile("cp.async.wait_group %0;\n" :: "n"(N));
}

// ---------------- prep ----------------
__global__ void __launch_bounds__(256) prep_kernel(const float* __restrict__ h_i,
                                                   const float* __restrict__ h_j,
                                                   const float* __restrict__ sub_x,
                                                   const float* __restrict__ all_x) {
    int tid = blockIdx.x * blockDim.x + threadIdx.x;
    int nth = gridDim.x * blockDim.x;

    int nh2 = NTOT * DDIM / 2;
    for (int idx = tid; idx < nh2; idx += nth) {
        int el  = idx << 1;
        int row = el >> 7;
        int col = el & 127;
        const float* src = (row < BHALF) ? (h_i + row * DDIM + col)
                                         : (h_j + (row - BHALF) * DDIM + col);
        float2 v = *reinterpret_cast<const float2*>(src);
        reinterpret_cast<__nv_bfloat162*>(g_h)[idx] = __floats2bfloat162_rn(v.x, v.y);
    }

    int wid = tid >> 5, lane = tid & 31, nw = nth >> 5;
    for (int r = wid; r < BHALF; r += nw) {
        float4 a = reinterpret_cast<const float4*>(sub_x + r * DDIM)[lane];
        float s = a.x*a.x + a.y*a.y + a.z*a.z + a.w*a.w;
        #pragma unroll
        for (int o = 16; o; o >>= 1) s += __shfl_xor_sync(0xffffffffu, s, o);
        if (lane == 0) g_xs2[r] = s;
    }
    for (int r = wid; r < KDIM; r += nw) {
        float4 a = reinterpret_cast<const float4*>(all_x + r * DDIM)[lane];
        float s = a.x*a.x + a.y*a.y + a.z*a.z + a.w*a.w;
        #pragma unroll
        for (int o = 16; o; o >>= 1) s += __shfl_xor_sync(0xffffffffu, s, o);
        if (lane == 0) g_ax2[r] = s;
    }

    for (int i = tid; i < KDIM; i += nth) g_c[i] = 0.f;
    if (blockIdx.x == 0 && tid < 4) g_acc[tid] = 0.f;
}

// ---------------- transpose all_x -> g_axT[d][k] ----------------
__global__ void __launch_bounds__(256) transpose_ax(const float* __restrict__ all_x) {
    __shared__ float t[32][33];
    int k0 = blockIdx.x * 32;
    int d0 = blockIdx.y * 32;
    int tx = threadIdx.x & 31, ty = threadIdx.x >> 5;
    #pragma unroll
    for (int j = 0; j < 4; j++) {
        int k = k0 + ty + j * 8;
        t[ty + j * 8][tx] = all_x[k * DDIM + d0 + tx];
    }
    __syncthreads();
    #pragma unroll
    for (int j = 0; j < 4; j++) {
        int d = d0 + ty + j * 8;
        g_axT[d * KDIM + k0 + tx] = __float2bfloat16(t[tx][ty + j * 8]);
    }
}

// ---------------- contrastive: cp.async pipelined, per-thread online LSE ----------------
#define CPAD 136

__global__ void __launch_bounds__(256) contrastive_kernel() {
    __shared__ __nv_bfloat16 Bs[2][64 * CPAD];
    __shared__ float st_m[64][2], st_s[64][2], st_p[64][2];

    int tid = threadIdx.x;
    int warp = tid >> 5, lane = tid & 31;
    int wm = warp >> 1, wn = warp & 1;
    int g = lane >> 2, tig = lane & 3;
    int rowBlock = blockIdx.x * 64;
    int r0 = wm * 16;
    int rowG0 = rowBlock + r0 + g;
    int lr0 = r0 + g, lr1 = r0 + g + 8;
    int p0 = (rowG0 + BHALF) & (NTOT - 1);
    int p1 = (rowG0 + 8 + BHALF) & (NTOT - 1);

    // A fragments straight from gmem (read-only, tiny)
    unsigned a_frag[8][4];
    #pragma unroll
    for (int ks = 0; ks < 8; ks++) {
        int kc = ks * 16 + tig * 2;
        a_frag[ks][0] = *reinterpret_cast<const unsigned*>(g_h + rowG0 * DDIM + kc);
        a_frag[ks][1] = *reinterpret_cast<const unsigned*>(g_h + (rowG0 + 8) * DDIM + kc);
        a_frag[ks][2] = *reinterpret_cast<const unsigned*>(g_h + rowG0 * DDIM + kc + 8);
        a_frag[ks][3] = *reinterpret_cast<const unsigned*>(g_h + (rowG0 + 8) * DDIM + kc + 8);
    }

    unsigned bsh[2];
    bsh[0] = (unsigned)__cvta_generic_to_shared(&Bs[0][0]);
    bsh[1] = (unsigned)__cvta_generic_to_shared(&Bs[1][0]);

    // prefetch tile 0
    #pragma unroll
    for (int j = 0; j < 4; j++) {
        int i = tid + j * 256;
        int r = i >> 4, c8 = i & 15;
        cp16(bsh[0] + (r * CPAD + c8 * 8) * 2, g_h + r * DDIM + c8 * 8);
    }
    cp_commit();

    float m0r = -CUDART_INF_F, m1r = -CUDART_INF_F;
    float s0r = 0.f, s1r = 0.f;
    float pos0 = -CUDART_INF_F, pos1 = -CUDART_INF_F;

    for (int ct = 0; ct < NTOT / 64; ct++) {
        int cur = ct & 1;
        if (ct + 1 < NTOT / 64) {
            #pragma unroll
            for (int j = 0; j < 4; j++) {
                int i = tid + j * 256;
                int r = i >> 4, c8 = i & 15;
                cp16(bsh[cur ^ 1] + (r * CPAD + c8 * 8) * 2,
                     g_h + ((ct + 1) * 64 + r) * DDIM + c8 * 8);
            }
            cp_commit();
            cp_wait<1>();
        } else {
            cp_wait<0>();
        }
        __syncthreads();

        float acc[4][4];
        #pragma unroll
        for (int nt = 0; nt < 4; nt++)
            acc[nt][0] = acc[nt][1] = acc[nt][2] = acc[nt][3] = 0.f;

        #pragma unroll
        for (int ks = 0; ks < 8; ks++) {
            #pragma unroll
            for (int nt = 0; nt < 4; nt++) {
                const __nv_bfloat16* bp = &Bs[cur][(wn * 32 + nt * 8 + g) * CPAD + ks * 16 + tig * 2];
                unsigned b0 = *reinterpret_cast<const unsigned*>(bp);
                unsigned b1 = *reinterpret_cast<const unsigned*>(bp + 8);
                mma_bf16(acc[nt], a_frag[ks], b0, b1);
            }
        }
        __syncthreads();   // compute done before next iteration overwrites Bs[cur]

        // per-thread epilogue: scale, positives, diag, online (m,s)
        float vv[2][8];
        #pragma unroll
        for (int nt = 0; nt < 4; nt++) {
            int jcol = ct * 64 + wn * 32 + nt * 8 + tig * 2;
            #pragma unroll
            for (int q = 0; q < 2; q++) {
                int jc = jcol + q;
                float x0 = acc[nt][q]     * 2.0f;
                float x1 = acc[nt][2 + q] * 2.0f;
                if (jc == p0) pos0 = x0;
                if (jc == p1) pos1 = x1;
                if (jc == rowG0)     x0 = -CUDART_INF_F;
                if (jc == rowG0 + 8) x1 = -CUDART_INF_F;
                vv[0][nt * 2 + q] = x0;
                vv[1][nt * 2 + q] = x1;
            }
        }
        {
            float tm0 = vv[0][0], tm1 = vv[1][0];
            #pragma unroll
            for (int q = 1; q < 8; q++) { tm0 = fmaxf(tm0, vv[0][q]); tm1 = fmaxf(tm1, vv[1][q]); }
            float nm0 = fmaxf(m0r, tm0), nm1 = fmaxf(m1r, tm1);
            float a0 = s0r * __expf(m0r - nm0);
            float a1 = s1r * __expf(m1r - nm1);
            #pragma unroll
            for (int q = 0; q < 8; q++) {
                a0 += __expf(vv[0][q] - nm0);
                a1 += __expf(vv[1][q] - nm1);
            }
            m0r = nm0; s0r = a0; m1r = nm1; s1r = a1;
        }
    }

    // merge across tig (offsets 1,2)
    #pragma unroll
    for (int o = 1; o <= 2; o <<= 1) {
        float mo = __shfl_xor_sync(0xffffffffu, m0r, o);
        float so = __shfl_xor_sync(0xffffffffu, s0r, o);
        float nm = fmaxf(m0r, mo);
        s0r = s0r * __expf(m0r - nm) + so * __expf(mo - nm); m0r = nm;
        mo = __shfl_xor_sync(0xffffffffu, m1r, o);
        so = __shfl_xor_sync(0xffffffffu, s1r, o);
        nm = fmaxf(m1r, mo);
        s1r = s1r * __expf(m1r - nm) + so * __expf(mo - nm); m1r = nm;
        pos0 = fmaxf(pos0, __shfl_xor_sync(0xffffffffu, pos0, o));
        pos1 = fmaxf(pos1, __shfl_xor_sync(0xffffffffu, pos1, o));
    }
    if (tig == 0) {
        st_m[lr0][wn] = m0r; st_s[lr0][wn] = s0r; st_p[lr0][wn] = pos0;
        st_m[lr1][wn] = m1r; st_s[lr1][wn] = s1r; st_p[lr1][wn] = pos1;
    }
    __syncthreads();

    float v = 0.f;
    if (tid < 64) {
        float ma = st_m[tid][0], sa = st_s[tid][0];
        float mb = st_m[tid][1], sb = st_s[tid][1];
        float nm = fmaxf(ma, mb);
        float s = sa * __expf(ma - nm) + sb * __expf(mb - nm);
        float p = fmaxf(st_p[tid][0], st_p[tid][1]);
        v = nm + logf(s) - p;
    }
    #pragma unroll
    for (int o = 16; o; o >>= 1) v += __shfl_xor_sync(0xffffffffu, v, o);
    if (tid < 64 && lane == 0) atomicAdd(&g_acc[0], v);
}

// ---------------- graph: direct-gmem A fragments, cp.async X tiles ----------------
#define KPX 40
#define GKSPLIT 8
#define GKS (KDIM / GKSPLIT)   // 1024

__global__ void __launch_bounds__(256, 2) graph_kernel(const float* __restrict__ G,
                                                       const float* __restrict__ sub_x) {
    __shared__ __nv_bfloat16 Xs[2][128 * KPX];
    __shared__ float c_loc[GKS];

    int tid = threadIdx.x;
    int warp = tid >> 5, lane = tid & 31;
    int g = lane >> 2, tig = lane & 3;
    int rb  = blockIdx.x & 31;
    int ksp = blockIdx.x >> 5;         // 0..7
    int rowBase = rb * 128;
    int kBase   = ksp * GKS;

    for (int i = tid; i < GKS; i += 256) c_loc[i] = 0.f;

    float acc[16][4];
    #pragma unroll
    for (int nt = 0; nt < 16; nt++)
        acc[nt][0] = acc[nt][1] = acc[nt][2] = acc[nt][3] = 0.f;
    float rsum0 = 0.f, rsum1 = 0.f;

    int r0 = warp * 16;
    int rowA = rowBase + r0 + g;
    int rowB = rowA + 8;
    const float* gRowA = G + (size_t)rowA * KDIM + kBase + tig * 2;
    const float* gRowB = G + (size_t)rowB * KDIM + kBase + tig * 2;

    unsigned xsh[2];
    xsh[0] = (unsigned)__cvta_generic_to_shared(&Xs[0][0]);
    xsh[1] = (unsigned)__cvta_generic_to_shared(&Xs[1][0]);

    // prefetch X tile 0
    #pragma unroll
    for (int j = 0; j < 2; j++) {
        int i = tid + j * 256;
        int d = i >> 2, q = i & 3;
        cp16(xsh[0] + (d * KPX + q * 8) * 2, g_axT + d * KDIM + kBase + q * 8);
    }
    cp_commit();

    // G register pipeline: one k-step (16 cols) ahead
    float2 bA0 = *reinterpret_cast<const float2*>(gRowA);
    float2 bB0 = *reinterpret_cast<const float2*>(gRowB);
    float2 bA1 = *reinterpret_cast<const float2*>(gRowA + 8);
    float2 bB1 = *reinterpret_cast<const float2*>(gRowB + 8);

    for (int kt = 0; kt < GKS / 32; kt++) {      // 32 X tiles
        int cur = kt & 1;
        if (kt + 1 < GKS / 32) {
            #pragma unroll
            for (int j = 0; j < 2; j++) {
                int i = tid + j * 256;
                int d = i >> 2, q = i & 3;
                cp16(xsh[cur ^ 1] + (d * KPX + q * 8) * 2,
                     g_axT + d * KDIM + kBase + (kt + 1) * 32 + q * 8);
            }
            cp_commit();
            cp_wait<1>();
        } else {
            cp_wait<0>();
        }
        __syncthreads();

        #pragma unroll
        for (int ks = 0; ks < 2; ks++) {
            int kk = kt * 2 + ks;
            float2 vA0 = bA0, vB0 = bB0, vA1 = bA1, vB1 = bB1;
            int ncol = (kk + 1 < GKS / 16) ? (kk + 1) * 16 : 0;   // clamp keeps last loads in-bounds
            bA0 = *reinterpret_cast<const float2*>(gRowA + ncol);
            bB0 = *reinterpret_cast<const float2*>(gRowB + ncol);
            bA1 = *reinterpret_cast<const float2*>(gRowA + ncol + 8);
            bB1 = *reinterpret_cast<const float2*>(gRowB + ncol + 8);

            rsum0 += vA0.x + vA0.y + vA1.x + vA1.y;
            rsum1 += vB0.x + vB0.y + vB1.x + vB1.y;

            float c0 = vA0.x + vB0.x, c1 = vA0.y + vB0.y;
            float c2 = vA1.x + vB1.x, c3 = vA1.y + vB1.y;
            #pragma unroll
            for (int o = 4; o <= 16; o <<= 1) {
                c0 += __shfl_xor_sync(0xffffffffu, c0, o);
                c1 += __shfl_xor_sync(0xffffffffu, c1, o);
                c2 += __shfl_xor_sync(0xffffffffu, c2, o);
                c3 += __shfl_xor_sync(0xffffffffu, c3, o);
            }
            if (lane < 4) {   // lane == tig, g == 0
                int cb = kt * 32 + ks * 16 + tig * 2;
                atomicAdd(&c_loc[cb],     c0);
                atomicAdd(&c_loc[cb + 1], c1);
                atomicAdd(&c_loc[cb + 8], c2);
                atomicAdd(&c_loc[cb + 9], c3);
            }

            unsigned af[4];
            af[0] = pack_bf2(vA0.x, vA0.y);
            af[1] = pack_bf2(vB0.x, vB0.y);
            af[2] = pack_bf2(vA1.x, vA1.y);
            af[3] = pack_bf2(vB1.x, vB1.y);
            #pragma unroll
            for (int nt = 0; nt < 16; nt++) {
                const __nv_bfloat16* bp = &Xs[cur][(nt * 8 + g) * KPX + ks * 16 + tig * 2];
                unsigned b0 = *reinterpret_cast<const unsigned*>(bp);
                unsigned b1 = *reinterpret_cast<const unsigned*>(bp + 8);
                mma_bf16(acc[nt], af, b0, b1);
            }
        }
        __syncthreads();
    }

    // flush column sums
    for (int i = tid; i < GKS; i += 256) atomicAdd(&g_c[kBase + i], c_loc[i]);

    // t3 partial
    float t3p = 0.f;
    #pragma unroll
    for (int nt = 0; nt < 16; nt++) {
        int d = nt * 8 + tig * 2;
        float2 s0 = *reinterpret_cast<const float2*>(sub_x + rowA * DDIM + d);
        float2 s1 = *reinterpret_cast<const float2*>(sub_x + rowB * DDIM + d);
        t3p += acc[nt][0] * s0.x + acc[nt][1] * s0.y + acc[nt][2] * s1.x + acc[nt][3] * s1.y;
    }
    #pragma unroll
    for (int o = 16; o; o >>= 1) t3p += __shfl_xor_sync(0xffffffffu, t3p, o);
    if (lane == 0) atomicAdd(&g_acc[2], t3p);

    // t1 partial
    rsum0 += __shfl_xor_sync(0xffffffffu, rsum0, 1);
    rsum0 += __shfl_xor_sync(0xffffffffu, rsum0, 2);
    rsum1 += __shfl_xor_sync(0xffffffffu, rsum1, 1);
    rsum1 += __shfl_xor_sync(0xffffffffu, rsum1, 2);
    float t1p = 0.f;
    if (tig == 0) t1p = rsum0 * g_xs2[rowA] + rsum1 * g_xs2[rowB];
    #pragma unroll
    for (int o = 4; o <= 16; o <<= 1) t1p += __shfl_xor_sync(0xffffffffu, t1p, o);
    if (lane == 0) atomicAdd(&g_acc[1], t1p);
}

// ---------------- finalize ----------------
__global__ void __launch_bounds__(256) finalize_kernel(float* __restrict__ out) {
    __shared__ float red[8];
    int tid = threadIdx.x;
    float t2 = 0.f;
    for (int k = tid; k < KDIM; k += 256) t2 += g_c[k] * g_ax2[k];
    #pragma unroll
    for (int o = 16; o; o >>= 1) t2 += __shfl_xor_sync(0xffffffffu, t2, o);
    if ((tid & 31) == 0) red[tid >> 5] = t2;
    __syncthreads();
    if (tid == 0) {
        float t2s = 0.f;
        #pragma unroll
        for (int i = 0; i < 8; i++) t2s += red[i];
        float contr = g_acc[0] / (float)NTOT;
        float graph = (g_acc[1] + t2s - 2.0f * g_acc[2]) / ((float)BHALF * (float)KDIM);
        out[0] = contr + graph;
    }
}

// ---------------- launch ----------------
extern "C" void kernel_launch(void* const* d_in, const int* in_sizes, int n_in,
                              void* d_out, int out_size) {
    (void)in_sizes; (void)n_in; (void)out_size;
    const float* h_i   = (const float*)d_in[0];
    const float* h_j   = (const float*)d_in[1];
    const float* G     = (const float*)d_in[2];
    const float* sub_x = (const float*)d_in[3];
    const float* all_x = (const float*)d_in[4];
    float* out = (float*)d_out;

    prep_kernel<<<512, 256>>>(h_i, h_j, sub_x, all_x);
    transpose_ax<<<dim3(256, 4), 256>>>(all_x);
    contrastive_kernel<<<128, 256>>>();
    graph_kernel<<<256, 256>>>(G, sub_x);
    finalize_kernel<<<1, 256>>>(out);
}

// round 9
// speedup vs baseline: 2.2470x; 1.1299x over previous
#include <cuda_runtime.h>
#include <cuda_bf16.h>
#include <math_constants.h>
#include <math.h>

#define NTOT  8192
#define BHALF 4096
#define DDIM  128
#define KDIM  8192

// ---------------- device scratch ----------------
__device__ __nv_bfloat16 g_h[NTOT * DDIM];
__device__ __nv_bfloat16 g_axT[DDIM * KDIM];
__device__ float g_xs2[BHALF];
__device__ float g_ax2[KDIM];
__device__ float g_acc[4];           // 1: t1, 2: t3, 3: t2
__device__ float g_lm[2 * NTOT];     // per-jsplit row max
__device__ float g_ls[2 * NTOT];     // per-jsplit row sumexp
__device__ float g_lp[2 * NTOT];     // per-jsplit row positive (-inf if absent)

// ---------------- helpers ----------------
__device__ __forceinline__ void mma_bf16(float* c, const unsigned* a, unsigned b0, unsigned b1) {
    asm volatile(
        "mma.sync.aligned.m16n8k16.row.col.f32.bf16.bf16.f32 "
        "{%0,%1,%2,%3}, {%4,%5,%6,%7}, {%8,%9}, {%0,%1,%2,%3};\n"
        : "+f"(c[0]), "+f"(c[1]), "+f"(c[2]), "+f"(c[3])
        : "r"(a[0]), "r"(a[1]), "r"(a[2]), "r"(a[3]), "r"(b0), "r"(b1));
}
__device__ __forceinline__ unsigned pack_bf2(float x, float y) {
    __nv_bfloat162 b = __floats2bfloat162_rn(x, y);
    return *reinterpret_cast<unsigned*>(&b);
}
__device__ __forceinline__ void cp16(unsigned dst, const void* src) {
    asm volatile("cp.async.cg.shared.global [%0], [%1], 16;\n" :: "r"(dst), "l"(src));
}
__device__ __forceinline__ void cp_commit() { asm volatile("cp.async.commit_group;\n"); }
template<int N> __device__ __forceinline__ void cp_wait() {
    asm volatile("cp.async.wait_group %0;\n" :: "n"(N));
}

// ---------------- prep ----------------
__global__ void __launch_bounds__(256) prep_kernel(const float* __restrict__ h_i,
                                                   const float* __restrict__ h_j,
                                                   const float* __restrict__ sub_x,
                                                   const float* __restrict__ all_x) {
    int tid = blockIdx.x * blockDim.x + threadIdx.x;
    int nth = gridDim.x * blockDim.x;

    int nh2 = NTOT * DDIM / 2;
    for (int idx = tid; idx < nh2; idx += nth) {
        int el  = idx << 1;
        int row = el >> 7;
        int col = el & 127;
        const float* src = (row < BHALF) ? (h_i + row * DDIM + col)
                                         : (h_j + (row - BHALF) * DDIM + col);
        float2 v = *reinterpret_cast<const float2*>(src);
        reinterpret_cast<__nv_bfloat162*>(g_h)[idx] = __floats2bfloat162_rn(v.x, v.y);
    }

    int wid = tid >> 5, lane = tid & 31, nw = nth >> 5;
    for (int r = wid; r < BHALF; r += nw) {
        float4 a = reinterpret_cast<const float4*>(sub_x + r * DDIM)[lane];
        float s = a.x*a.x + a.y*a.y + a.z*a.z + a.w*a.w;
        #pragma unroll
        for (int o = 16; o; o >>= 1) s += __shfl_xor_sync(0xffffffffu, s, o);
        if (lane == 0) g_xs2[r] = s;
    }
    for (int r = wid; r < KDIM; r += nw) {
        float4 a = reinterpret_cast<const float4*>(all_x + r * DDIM)[lane];
        float s = a.x*a.x + a.y*a.y + a.z*a.z + a.w*a.w;
        #pragma unroll
        for (int o = 16; o; o >>= 1) s += __shfl_xor_sync(0xffffffffu, s, o);
        if (lane == 0) g_ax2[r] = s;
    }

    if (blockIdx.x == 0 && tid < 4) g_acc[tid] = 0.f;
}

// ---------------- transpose all_x -> g_axT[d][k] ----------------
__global__ void __launch_bounds__(256) transpose_ax(const float* __restrict__ all_x) {
    __shared__ float t[32][33];
    int k0 = blockIdx.x * 32;
    int d0 = blockIdx.y * 32;
    int tx = threadIdx.x & 31, ty = threadIdx.x >> 5;
    #pragma unroll
    for (int j = 0; j < 4; j++) {
        int k = k0 + ty + j * 8;
        t[ty + j * 8][tx] = all_x[k * DDIM + d0 + tx];
    }
    __syncthreads();
    #pragma unroll
    for (int j = 0; j < 4; j++) {
        int d = d0 + ty + j * 8;
        g_axT[d * KDIM + k0 + tx] = __float2bfloat16(t[tx][ty + j * 8]);
    }
}

// ---------------- contrastive: j-split x2, cp.async pipelined, per-thread LSE ----------------
#define CPAD 136
#define NJT  64   // 64 column tiles of 64 per j-split

__global__ void __launch_bounds__(256, 2) contrastive_kernel() {
    __shared__ __nv_bfloat16 Bs[2][64 * CPAD];
    __shared__ float st_m[64][2], st_s[64][2], st_p[64][2];

    int tid = threadIdx.x;
    int warp = tid >> 5, lane = tid & 31;
    int wm = warp >> 1, wn = warp & 1;
    int g = lane >> 2, tig = lane & 3;
    int rb = blockIdx.x & 127;
    int js = blockIdx.x >> 7;           // 0 or 1
    int jsBase = js * (NTOT / 2);
    int rowBlock = rb * 64;
    int r0 = wm * 16;
    int rowG0 = rowBlock + r0 + g;
    int lr0 = r0 + g, lr1 = r0 + g + 8;
    int p0 = (rowG0 + BHALF) & (NTOT - 1);
    int p1 = (rowG0 + 8 + BHALF) & (NTOT - 1);

    unsigned a_frag[8][4];
    #pragma unroll
    for (int ks = 0; ks < 8; ks++) {
        int kc = ks * 16 + tig * 2;
        a_frag[ks][0] = *reinterpret_cast<const unsigned*>(g_h + rowG0 * DDIM + kc);
        a_frag[ks][1] = *reinterpret_cast<const unsigned*>(g_h + (rowG0 + 8) * DDIM + kc);
        a_frag[ks][2] = *reinterpret_cast<const unsigned*>(g_h + rowG0 * DDIM + kc + 8);
        a_frag[ks][3] = *reinterpret_cast<const unsigned*>(g_h + (rowG0 + 8) * DDIM + kc + 8);
    }

    unsigned bsh[2];
    bsh[0] = (unsigned)__cvta_generic_to_shared(&Bs[0][0]);
    bsh[1] = (unsigned)__cvta_generic_to_shared(&Bs[1][0]);

    // prefetch tile 0
    #pragma unroll
    for (int j = 0; j < 4; j++) {
        int i = tid + j * 256;
        int r = i >> 4, c8 = i & 15;
        cp16(bsh[0] + (r * CPAD + c8 * 8) * 2, g_h + (jsBase + r) * DDIM + c8 * 8);
    }
    cp_commit();

    float m0r = -CUDART_INF_F, m1r = -CUDART_INF_F;
    float s0r = 0.f, s1r = 0.f;
    float pos0 = -CUDART_INF_F, pos1 = -CUDART_INF_F;

    for (int ct = 0; ct < NJT; ct++) {
        int cur = ct & 1;
        __syncthreads();                       // all reads of Bs[cur^1] (prev tile) done
        if (ct + 1 < NJT) {
            #pragma unroll
            for (int j = 0; j < 4; j++) {
                int i = tid + j * 256;
                int r = i >> 4, c8 = i & 15;
                cp16(bsh[cur ^ 1] + (r * CPAD + c8 * 8) * 2,
                     g_h + (jsBase + (ct + 1) * 64 + r) * DDIM + c8 * 8);
            }
            cp_commit();
            cp_wait<1>();
        } else {
            cp_wait<0>();
        }
        __syncthreads();                       // Bs[cur] writes visible to ALL threads

        float acc[4][4];
        #pragma unroll
        for (int nt = 0; nt < 4; nt++)
            acc[nt][0] = acc[nt][1] = acc[nt][2] = acc[nt][3] = 0.f;

        #pragma unroll
        for (int ks = 0; ks < 8; ks++) {
            #pragma unroll
            for (int nt = 0; nt < 4; nt++) {
                const __nv_bfloat16* bp = &Bs[cur][(wn * 32 + nt * 8 + g) * CPAD + ks * 16 + tig * 2];
                unsigned b0 = *reinterpret_cast<const unsigned*>(bp);
                unsigned b1 = *reinterpret_cast<const unsigned*>(bp + 8);
                mma_bf16(acc[nt], a_frag[ks], b0, b1);
            }
        }

        float vv[2][8];
        #pragma unroll
        for (int nt = 0; nt < 4; nt++) {
            int jcol = jsBase + ct * 64 + wn * 32 + nt * 8 + tig * 2;
            #pragma unroll
            for (int q = 0; q < 2; q++) {
                int jc = jcol + q;
                float x0 = acc[nt][q]     * 2.0f;
                float x1 = acc[nt][2 + q] * 2.0f;
                if (jc == p0) pos0 = x0;
                if (jc == p1) pos1 = x1;
                if (jc == rowG0)     x0 = -CUDART_INF_F;
                if (jc == rowG0 + 8) x1 = -CUDART_INF_F;
                vv[0][nt * 2 + q] = x0;
                vv[1][nt * 2 + q] = x1;
            }
        }
        {
            float tm0 = vv[0][0], tm1 = vv[1][0];
            #pragma unroll
            for (int q = 1; q < 8; q++) { tm0 = fmaxf(tm0, vv[0][q]); tm1 = fmaxf(tm1, vv[1][q]); }
            float nm0 = fmaxf(m0r, tm0), nm1 = fmaxf(m1r, tm1);
            float a0 = s0r * __expf(m0r - nm0);
            float a1 = s1r * __expf(m1r - nm1);
            #pragma unroll
            for (int q = 0; q < 8; q++) {
                a0 += __expf(vv[0][q] - nm0);
                a1 += __expf(vv[1][q] - nm1);
            }
            m0r = nm0; s0r = a0; m1r = nm1; s1r = a1;
        }
    }

    // merge across tig
    #pragma unroll
    for (int o = 1; o <= 2; o <<= 1) {
        float mo = __shfl_xor_sync(0xffffffffu, m0r, o);
        float so = __shfl_xor_sync(0xffffffffu, s0r, o);
        float nm = fmaxf(m0r, mo);
        s0r = s0r * __expf(m0r - nm) + so * __expf(mo - nm); m0r = nm;
        mo = __shfl_xor_sync(0xffffffffu, m1r, o);
        so = __shfl_xor_sync(0xffffffffu, s1r, o);
        nm = fmaxf(m1r, mo);
        s1r = s1r * __expf(m1r - nm) + so * __expf(mo - nm); m1r = nm;
        pos0 = fmaxf(pos0, __shfl_xor_sync(0xffffffffu, pos0, o));
        pos1 = fmaxf(pos1, __shfl_xor_sync(0xffffffffu, pos1, o));
    }
    if (tig == 0) {
        st_m[lr0][wn] = m0r; st_s[lr0][wn] = s0r; st_p[lr0][wn] = pos0;
        st_m[lr1][wn] = m1r; st_s[lr1][wn] = s1r; st_p[lr1][wn] = pos1;
    }
    __syncthreads();

    if (tid < 64) {
        float ma = st_m[tid][0], sa = st_s[tid][0];
        float mb = st_m[tid][1], sb = st_s[tid][1];
        float nm = fmaxf(ma, mb);
        float s = sa * __expf(ma - nm) + sb * __expf(mb - nm);
        int row = js * NTOT + rowBlock + tid;
        g_lm[row] = nm;
        g_ls[row] = s;
        g_lp[row] = fmaxf(st_p[tid][0], st_p[tid][1]);
    }
}

// ---------------- graph: direct-gmem A fragments, t2 fused in-register ----------------
#define KPX 40
#define GKSPLIT 8
#define GKS (KDIM / GKSPLIT)   // 1024

__global__ void __launch_bounds__(256, 2) graph_kernel(const float* __restrict__ G,
                                                       const float* __restrict__ sub_x) {
    __shared__ __nv_bfloat16 Xs[2][128 * KPX];

    int tid = threadIdx.x;
    int warp = tid >> 5, lane = tid & 31;
    int g = lane >> 2, tig = lane & 3;
    int rb  = blockIdx.x & 31;
    int ksp = blockIdx.x >> 5;
    int rowBase = rb * 128;
    int kBase   = ksp * GKS;

    float acc[16][4];
    #pragma unroll
    for (int nt = 0; nt < 16; nt++)
        acc[nt][0] = acc[nt][1] = acc[nt][2] = acc[nt][3] = 0.f;
    float rsum0 = 0.f, rsum1 = 0.f, t2p = 0.f;

    int r0 = warp * 16;
    int rowA = rowBase + r0 + g;
    int rowB = rowA + 8;
    const float* gRowA = G + (size_t)rowA * KDIM + kBase + tig * 2;
    const float* gRowB = G + (size_t)rowB * KDIM + kBase + tig * 2;
    const float* axp   = g_ax2 + kBase + tig * 2;

    unsigned xsh[2];
    xsh[0] = (unsigned)__cvta_generic_to_shared(&Xs[0][0]);
    xsh[1] = (unsigned)__cvta_generic_to_shared(&Xs[1][0]);

    #pragma unroll
    for (int j = 0; j < 2; j++) {
        int i = tid + j * 256;
        int d = i >> 2, q = i & 3;
        cp16(xsh[0] + (d * KPX + q * 8) * 2, g_axT + d * KDIM + kBase + q * 8);
    }
    cp_commit();

    float2 bA0 = *reinterpret_cast<const float2*>(gRowA);
    float2 bB0 = *reinterpret_cast<const float2*>(gRowB);
    float2 bA1 = *reinterpret_cast<const float2*>(gRowA + 8);
    float2 bB1 = *reinterpret_cast<const float2*>(gRowB + 8);

    for (int kt = 0; kt < GKS / 32; kt++) {
        int cur = kt & 1;
        __syncthreads();                       // all reads of Xs[cur^1] (prev tile) done
        if (kt + 1 < GKS / 32) {
            #pragma unroll
            for (int j = 0; j < 2; j++) {
                int i = tid + j * 256;
                int d = i >> 2, q = i & 3;
                cp16(xsh[cur ^ 1] + (d * KPX + q * 8) * 2,
                     g_axT + d * KDIM + kBase + (kt + 1) * 32 + q * 8);
            }
            cp_commit();
            cp_wait<1>();
        } else {
            cp_wait<0>();
        }
        __syncthreads();                       // Xs[cur] writes visible to ALL threads

        #pragma unroll
        for (int ks = 0; ks < 2; ks++) {
            int kk = kt * 2 + ks;
            float2 vA0 = bA0, vB0 = bB0, vA1 = bA1, vB1 = bB1;
            int ncol = (kk + 1 < GKS / 16) ? (kk + 1) * 16 : 0;
            bA0 = *reinterpret_cast<const float2*>(gRowA + ncol);
            bB0 = *reinterpret_cast<const float2*>(gRowB + ncol);
            bA1 = *reinterpret_cast<const float2*>(gRowA + ncol + 8);
            bB1 = *reinterpret_cast<const float2*>(gRowB + ncol + 8);

            rsum0 += vA0.x + vA0.y + vA1.x + vA1.y;
            rsum1 += vB0.x + vB0.y + vB1.x + vB1.y;

            // t2 partial: (row contributions) . ax2  (broadcast loads, L1-resident)
            float2 w0 = *reinterpret_cast<const float2*>(axp + kk * 16);
            float2 w1 = *reinterpret_cast<const float2*>(axp + kk * 16 + 8);
            t2p += (vA0.x + vB0.x) * w0.x + (vA0.y + vB0.y) * w0.y
                 + (vA1.x + vB1.x) * w1.x + (vA1.y + vB1.y) * w1.y;

            unsigned af[4];
            af[0] = pack_bf2(vA0.x, vA0.y);
            af[1] = pack_bf2(vB0.x, vB0.y);
            af[2] = pack_bf2(vA1.x, vA1.y);
            af[3] = pack_bf2(vB1.x, vB1.y);
            #pragma unroll
            for (int nt = 0; nt < 16; nt++) {
                const __nv_bfloat16* bp = &Xs[cur][(nt * 8 + g) * KPX + ks * 16 + tig * 2];
                unsigned b0 = *reinterpret_cast<const unsigned*>(bp);
                unsigned b1 = *reinterpret_cast<const unsigned*>(bp + 8);
                mma_bf16(acc[nt], af, b0, b1);
            }
        }
    }

    // t3 partial
    float t3p = 0.f;
    #pragma unroll
    for (int nt = 0; nt < 16; nt++) {
        int d = nt * 8 + tig * 2;
        float2 s0 = *reinterpret_cast<const float2*>(sub_x + rowA * DDIM + d);
        float2 s1 = *reinterpret_cast<const float2*>(sub_x + rowB * DDIM + d);
        t3p += acc[nt][0] * s0.x + acc[nt][1] * s0.y + acc[nt][2] * s1.x + acc[nt][3] * s1.y;
    }
    #pragma unroll
    for (int o = 16; o; o >>= 1) t3p += __shfl_xor_sync(0xffffffffu, t3p, o);
    if (lane == 0) atomicAdd(&g_acc[2], t3p);

    // t2 partial
    #pragma unroll
    for (int o = 16; o; o >>= 1) t2p += __shfl_xor_sync(0xffffffffu, t2p, o);
    if (lane == 0) atomicAdd(&g_acc[3], t2p);

    // t1 partial
    rsum0 += __shfl_xor_sync(0xffffffffu, rsum0, 1);
    rsum0 += __shfl_xor_sync(0xffffffffu, rsum0, 2);
    rsum1 += __shfl_xor_sync(0xffffffffu, rsum1, 1);
    rsum1 += __shfl_xor_sync(0xffffffffu, rsum1, 2);
    float t1p = 0.f;
    if (tig == 0) t1p = rsum0 * g_xs2[rowA] + rsum1 * g_xs2[rowB];
    #pragma unroll
    for (int o = 4; o <= 16; o <<= 1) t1p += __shfl_xor_sync(0xffffffffu, t1p, o);
    if (lane == 0) atomicAdd(&g_acc[1], t1p);
}

// ---------------- finalize: LSE merge + combine ----------------
__global__ void __launch_bounds__(256) finalize_kernel(float* __restrict__ out) {
    __shared__ float red[8];
    int tid = threadIdx.x;
    float csum = 0.f;
    for (int r = tid; r < NTOT; r += 256) {
        float m0 = g_lm[r],        s0 = g_ls[r];
        float m1 = g_lm[NTOT + r], s1 = g_ls[NTOT + r];
        float nm = fmaxf(m0, m1);
        float s = s0 * __expf(m0 - nm) + s1 * __expf(m1 - nm);
        float p = fmaxf(g_lp[r], g_lp[NTOT + r]);
        csum += nm + logf(s) - p;
    }
    #pragma unroll
    for (int o = 16; o; o >>= 1) csum += __shfl_xor_sync(0xffffffffu, csum, o);
    if ((tid & 31) == 0) red[tid >> 5] = csum;
    __syncthreads();
    if (tid == 0) {
        float cs = 0.f;
        #pragma unroll
        for (int i = 0; i < 8; i++) cs += red[i];
        float contr = cs / (float)NTOT;
        float graph = (g_acc[1] + g_acc[3] - 2.0f * g_acc[2]) / ((float)BHALF * (float)KDIM);
        out[0] = contr + graph;
    }
}

// ---------------- launch ----------------
extern "C" void kernel_launch(void* const* d_in, const int* in_sizes, int n_in,
                              void* d_out, int out_size) {
    (void)in_sizes; (void)n_in; (void)out_size;
    const float* h_i   = (const float*)d_in[0];
    const float* h_j   = (const float*)d_in[1];
    const float* G     = (const float*)d_in[2];
    const float* sub_x = (const float*)d_in[3];
    const float* all_x = (const float*)d_in[4];
    float* out = (float*)d_out;

    prep_kernel<<<512, 256>>>(h_i, h_j, sub_x, all_x);
    transpose_ax<<<dim3(256, 4), 256>>>(all_x);
    contrastive_kernel<<<256, 256>>>();
    graph_kernel<<<256, 256>>>(G, sub_x);
    finalize_kernel<<<1, 256>>>(out);
}